// round 6
// baseline (speedup 1.0000x reference)
#include <cuda_runtime.h>

// Problem constants
#define NB 16
#define NS 128
#define NC 64
#define NH 8
#define NHD 64
#define ND 512
#define NM 256   // D/2

// Role layout in the single grid
#define N_PBLK 16          // P-partial producer blocks
#define BID_SCAL 16        // scalar block
#define N_PRE 17           // producers counted in ctr1
#define N_QBLK 8           // Q blocks
#define BID_Q0 17
#define BID_MAIN0 25
#define N_MAIN (NB * NC)   // 1024
#define GRID_TOT (BID_MAIN0 + N_MAIN)   // 1049

// ---------------- scratch (device globals; zero-initialized) ----------------
__device__ float g_sA[NH];           // scale * (Wq_h . Wk_h)
__device__ float g_sC[NH];           // scale * (bq_h . Wk_h)
__device__ float g_Pp[16 * NM];      // P partials per (head, row-half)
__device__ float g_p0q[16 * NM];     // p0 partials (bv @ Ws)
__device__ float g_Q[NH * ND];       // folded SE matrix
__device__ float g_q0[ND];
__device__ float g_R[ND];            // Wv * Wf
__device__ float g_r0[ND];           // bv * Wf
__device__ int   g_ctr1, g_ctr2, g_done;   // phase counters (reset each launch)

__device__ __forceinline__ float warp_sum(float v) {
#pragma unroll
    for (int o = 16; o; o >>= 1) v += __shfl_xor_sync(0xffffffffu, v, o);
    return v;
}

// shared-memory role union
struct SmP { float sWv[32], sbv[32]; };
struct SmS { float accA[NH], accC[NH]; };
struct SmQ { float sc[9][NM]; float red[3][9][64]; };
struct SmM {
    float xs[NS]; float xv[NH][NS]; float exc[ND];
    float sA[NH], sC[NH], sqv[NH], w1[NH];
    float cN[NH][10], cD[NH][10];
    float red[8]; float smax, smin, w0t;
};

__global__ void __launch_bounds__(256, 8) k_fused(
    const float* __restrict__ x,
    const float* __restrict__ Wq, const float* __restrict__ bq,
    const float* __restrict__ Wk,
    const float* __restrict__ Wv, const float* __restrict__ bv,
    const float* __restrict__ Ws, const float* __restrict__ bs,
    const float* __restrict__ We, const float* __restrict__ be,
    const float* __restrict__ Wf, const float* __restrict__ bf,
    float* __restrict__ out)
{
    __shared__ union { SmP p; SmS s; SmQ q; SmM m; } sm;
    int t = threadIdx.x;
    int bid = blockIdx.x;

    // ======================= phase 1: producers =============================
    if (bid < N_PBLK) {
        // P partials: head = bid>>1, row-half = bid&1 (32 rows of Ws)
        int row0 = bid * 32;
        if (t < 32) {
            sm.p.sWv[t] = Wv[row0 + t];
            sm.p.sbv[t] = bv[row0 + t];
        }
        __syncthreads();
        const float* wsp = Ws + (size_t)row0 * NM + t;
        float accP = 0.f, acc0 = 0.f;
#pragma unroll
        for (int r0 = 0; r0 < 32; r0 += 16) {
            float wv[16];
#pragma unroll
            for (int u = 0; u < 16; u++)
                wv[u] = wsp[(size_t)(r0 + u) * NM];
#pragma unroll
            for (int u = 0; u < 16; u++) {
                accP = fmaf(sm.p.sWv[r0 + u], wv[u], accP);
                acc0 = fmaf(sm.p.sbv[r0 + u], wv[u], acc0);
            }
        }
        g_Pp[bid * NM + t]  = accP;
        g_p0q[bid * NM + t] = acc0;
        __threadfence();
        __syncthreads();
        if (t == 0) atomicAdd(&g_ctr1, 1);
        return;
    }

    if (bid == BID_SCAL) {
        if (t < NH) { sm.s.accA[t] = 0.f; sm.s.accC[t] = 0.f; }
        __syncthreads();
        int lane = t & 31;
#pragma unroll
        for (int seg = 0; seg < 2; seg++) {
            int d = t + seg * 256;
            float a = Wq[d] * Wk[d];
            float c = bq[d] * Wk[d];
            a = warp_sum(a);
            c = warp_sum(c);
            if (lane == 0) {
                int h = d >> 6;
                atomicAdd(&sm.s.accA[h], a);
                atomicAdd(&sm.s.accC[h], c);
            }
            g_R[d]  = Wv[d] * Wf[d];
            g_r0[d] = bv[d] * Wf[d];
        }
        __syncthreads();
        if (t < NH) {
            g_sA[t] = sm.s.accA[t] * 0.125f;   // 1/sqrt(64)
            g_sC[t] = sm.s.accC[t] * 0.125f;
        }
        __threadfence();
        __syncthreads();
        if (t == 0) atomicAdd(&g_ctr1, 1);
        return;
    }

    // ======================= phase 2: Q blocks ==============================
    if (bid < BID_MAIN0) {
        // wait for all producers
        if (t == 0) {
            while (*(volatile int*)&g_ctr1 < N_PRE) __nanosleep(128);
        }
        __syncthreads();
        __threadfence();

        int qb = bid - BID_Q0;          // 0..7
        int d0 = (qb & 1) * 256;        // d half... need 512/8 split: use (qb>>?) below
        // 8 blocks: d-chunk = qb>>0? Use: d0 = (qb & 7) * 64  -> 8 chunks of 64 d
        d0 = qb * 64;
        int dl = t & 63;                // 0..63 within chunk
        int mq = t >> 6;                // 0..3 m-quarter

        // stage P (pairwise, fixed order) and p0 (16 partials, fixed order)
        for (int idx = t; idx < 9 * NM; idx += 256) {
            int row = idx >> 8;
            int m   = idx & 255;
            if (row < NH) {
                sm.q.sc[row][m] = g_Pp[(2 * row) * NM + m] + g_Pp[(2 * row + 1) * NM + m];
            } else {
                float s = bs[m];
#pragma unroll
                for (int k = 0; k < 16; k++) s += g_p0q[k * NM + m];
                sm.q.sc[8][m] = s;
            }
        }
        __syncthreads();

        int d = d0 + dl;
        float acc[9];
#pragma unroll
        for (int i = 0; i < 9; i++) acc[i] = 0.f;

        const float* wp = We + d;
        int mbase = mq * 64;
#pragma unroll
        for (int m0 = 0; m0 < 64; m0 += 8) {
            float wv[8];
#pragma unroll
            for (int u = 0; u < 8; u++)
                wv[u] = wp[(size_t)(mbase + m0 + u) * ND];
#pragma unroll
            for (int u = 0; u < 8; u++) {
#pragma unroll
                for (int i = 0; i < 9; i++)
                    acc[i] = fmaf(sm.q.sc[i][mbase + m0 + u], wv[u], acc[i]);
            }
        }

        if (mq > 0) {
#pragma unroll
            for (int i = 0; i < 9; i++) sm.q.red[mq - 1][i][dl] = acc[i];
        }
        __syncthreads();
        if (mq == 0) {
#pragma unroll
            for (int i = 0; i < 9; i++)
                acc[i] = ((acc[i] + sm.q.red[0][i][dl]) + sm.q.red[1][i][dl]) + sm.q.red[2][i][dl];
#pragma unroll
            for (int h = 0; h < NH; h++) g_Q[h * ND + d] = acc[h];
            g_q0[d] = acc[8] + be[d];
        }
        __threadfence();
        __syncthreads();
        if (t == 0) atomicAdd(&g_ctr2, 1);
        return;
    }

    // ======================= phase 3: main ==================================
    {
        if (t == 0) {
            while (*(volatile int*)&g_ctr2 < N_QBLK) __nanosleep(128);
        }
        __syncthreads();
        __threadfence();

        int idx = bid - BID_MAIN0;
        int c = idx & (NC - 1);
        int b = idx >> 6;
        int lane = t & 31;
        int w = t >> 5;
        const float* xp = x + (size_t)(b * NS) * NC + c;

        if (t < NS) sm.m.xs[t] = xp[t * NC];
        if (t < NH) { sm.m.sA[t] = g_sA[t]; sm.m.sC[t] = g_sC[t]; }
        __syncthreads();

        // min/max -> expansion center
        if (t < 32) {
            float mx = -1e30f, mn = 1e30f;
#pragma unroll
            for (int k = t; k < NS; k += 32) {
                float v = sm.m.xs[k];
                mx = fmaxf(mx, v);
                mn = fminf(mn, v);
            }
#pragma unroll
            for (int o = 16; o; o >>= 1) {
                mx = fmaxf(mx, __shfl_xor_sync(0xffffffffu, mx, o));
                mn = fminf(mn, __shfl_xor_sync(0xffffffffu, mn, o));
            }
            if (t == 0) { sm.m.smax = mx; sm.m.smin = mn; }
        }
        __syncthreads();

        float xmid = 0.5f * (sm.m.smax + sm.m.smin);

        // Stage A: per-head weighted moments
        {
            float bc = fmaf(sm.m.sA[w], xmid, sm.m.sC[w]);
            float m[11];
#pragma unroll
            for (int n = 0; n < 11; n++) m[n] = 0.f;
#pragma unroll
            for (int j = 0; j < 4; j++) {
                float xk = sm.m.xs[lane + 32 * j];
                float p = __expf(bc * xk);
#pragma unroll
                for (int n = 0; n < 11; n++) { m[n] += p; p *= xk; }
            }
#pragma unroll
            for (int n = 0; n < 11; n++) m[n] = warp_sum(m[n]);
            if (lane == 0) {
                const float invf[10] = {1.f, 1.f, 0.5f, 1.f/6.f, 1.f/24.f, 1.f/120.f,
                                        1.f/720.f, 1.f/5040.f, 1.f/40320.f, 1.f/362880.f};
#pragma unroll
                for (int n = 0; n < 10; n++) {
                    sm.m.cD[w][n] = m[n]     * invf[n];
                    sm.m.cN[w][n] = m[n + 1] * invf[n];
                }
            }
        }
        __syncthreads();

        // Stage B: rational evaluation per (h,q)
#pragma unroll
        for (int p = t; p < NH * NS; p += 256) {
            int h = p >> 7;
            int q = p & (NS - 1);
            float dl = sm.m.sA[h] * (sm.m.xs[q] - xmid);
            float num = sm.m.cN[h][9];
            float den = sm.m.cD[h][9];
#pragma unroll
            for (int n = 8; n >= 0; n--) {
                num = fmaf(num, dl, sm.m.cN[h][n]);
                den = fmaf(den, dl, sm.m.cD[h][n]);
            }
            sm.m.xv[h][q] = __fdividef(num, den);
        }
        __syncthreads();

        // squeeze
        {
            float s = sm.m.xv[w][lane] + sm.m.xv[w][lane + 32]
                    + sm.m.xv[w][lane + 64] + sm.m.xv[w][lane + 96];
            s = warp_sum(s);
            if (lane == 0) sm.m.sqv[w] = s * (1.0f / NS);
        }
        __syncthreads();

        // excitation
        for (int d = t; d < ND; d += 256) {
            float u = g_q0[d];
#pragma unroll
            for (int h = 0; h < NH; h++)
                u = fmaf(sm.m.sqv[h], g_Q[h * ND + d], u);
            sm.m.exc[d] = __fdividef(1.0f, 1.0f + __expf(-u));
        }
        __syncthreads();

        // output projection folds
        {
            int d0 = w * NHD + lane;
            float s = g_R[d0] * sm.m.exc[d0] + g_R[d0 + 32] * sm.m.exc[d0 + 32];
            s = warp_sum(s);
            if (lane == 0) sm.m.w1[w] = s;
        }
        {
            float pv = g_r0[t] * sm.m.exc[t] + g_r0[t + 256] * sm.m.exc[t + 256];
            pv = warp_sum(pv);
            if (lane == 0) sm.m.red[w] = pv;
        }
        __syncthreads();
        if (t == 0) {
            float s = 0.f;
#pragma unroll
            for (int i = 0; i < 8; i++) s += sm.m.red[i];
            sm.m.w0t = s + bf[0];
        }
        __syncthreads();

        if (t < NS) {
            float o = sm.m.w0t;
#pragma unroll
            for (int h = 0; h < NH; h++)
                o = fmaf(sm.m.xv[h][t], sm.m.w1[h], o);
            out[(size_t)(b * NS + t) * NC + c] = o;
        }

        // completion + counter reset by the last main block (for next launch)
        __syncthreads();
        if (t == 0) {
            int v = atomicAdd(&g_done, 1);
            if (v == N_MAIN - 1) {
                g_ctr1 = 0;
                g_ctr2 = 0;
                g_done = 0;
            }
        }
    }
}

// ---------------- launch ----------------------------------------------------
extern "C" void kernel_launch(void* const* d_in, const int* in_sizes, int n_in,
                              void* d_out, int out_size)
{
    const float* x  = (const float*)d_in[0];
    const float* Wq = (const float*)d_in[1];
    const float* bq = (const float*)d_in[2];
    const float* Wk = (const float*)d_in[3];
    // d_in[4] = bk: cancels under softmax, unused
    const float* Wv = (const float*)d_in[5];
    const float* bv = (const float*)d_in[6];
    const float* Ws = (const float*)d_in[7];
    const float* bs = (const float*)d_in[8];
    const float* We = (const float*)d_in[9];
    const float* be = (const float*)d_in[10];
    const float* Wf = (const float*)d_in[11];
    const float* bf = (const float*)d_in[12];
    float* out = (float*)d_out;

    k_fused<<<GRID_TOT, 256>>>(x, Wq, bq, Wk, Wv, bv, Ws, bs, We, be, Wf, bf, out);
}

// round 7
// speedup vs baseline: 1.2008x; 1.2008x over previous
#include <cuda_runtime.h>

// Problem constants
#define NB 16
#define NS 128
#define NC 64
#define NH 8
#define NHD 64
#define ND 512
#define NM 256   // D/2

// Role layout in the single grid
#define BID_SCAL 0
#define BID_P0 1
#define N_PBLK 16
#define BID_Q0 17
#define N_QBLK 8
#define BID_MAIN0 25
#define N_MAIN (NB * NC)                 // 1024
#define GRID_TOT (BID_MAIN0 + N_MAIN)    // 1049

// ---------------- scratch (device globals; zero-initialized) ----------------
__device__ float g_sA[NH];           // scale * (Wq_h . Wk_h)
__device__ float g_sC[NH];           // scale * (bq_h . Wk_h)
__device__ float g_Pp[16 * NM];      // P partials per (head, row-half)
__device__ float g_p0q[16 * NM];     // p0 partials (bv @ Ws)
__device__ float g_Q[NH * ND];       // folded SE matrix
__device__ float g_q0[ND];
__device__ float g_R[ND];            // Wv * Wf
__device__ float g_r0[ND];           // bv * Wf
__device__ int   g_cs, g_cp, g_cq, g_done;   // phase counters (reset each launch)

__device__ __forceinline__ float warp_sum(float v) {
#pragma unroll
    for (int o = 16; o; o >>= 1) v += __shfl_xor_sync(0xffffffffu, v, o);
    return v;
}

__device__ __forceinline__ void spin_until(volatile int* ctr, int target) {
    while (*ctr < target) __nanosleep(64);
}

// shared-memory role union
struct SmP { float sWv[32], sbv[32]; };
struct SmS { float accA[NH], accC[NH]; };
struct SmQ { float sc[9][NM]; float red[3][9][64]; };
struct SmM {
    float xs[NS]; float xv[NH][NS]; float exc[ND];
    float sA[NH], sC[NH], sqv[NH], w1[NH];
    float cN[NH][10], cD[NH][10];
    float red[8]; float smax, smin, w0t;
};

__global__ void __launch_bounds__(256, 8) k_fused(
    const float* __restrict__ x,
    const float* __restrict__ Wq, const float* __restrict__ bq,
    const float* __restrict__ Wk,
    const float* __restrict__ Wv, const float* __restrict__ bv,
    const float* __restrict__ Ws, const float* __restrict__ bs,
    const float* __restrict__ We, const float* __restrict__ be,
    const float* __restrict__ Wf, const float* __restrict__ bf,
    float* __restrict__ out)
{
    __shared__ union { SmP p; SmS s; SmQ q; SmM m; } sm;
    int t = threadIdx.x;
    int bid = blockIdx.x;

    // ============ scalar block: sA/sC + R/r0 (main's only early dep) ========
    if (bid == BID_SCAL) {
        if (t < NH) { sm.s.accA[t] = 0.f; sm.s.accC[t] = 0.f; }
        __syncthreads();
        int lane = t & 31;
#pragma unroll
        for (int seg = 0; seg < 2; seg++) {
            int d = t + seg * 256;
            float a = Wq[d] * Wk[d];
            float c = bq[d] * Wk[d];
            a = warp_sum(a);
            c = warp_sum(c);
            if (lane == 0) {
                int h = d >> 6;
                atomicAdd(&sm.s.accA[h], a);
                atomicAdd(&sm.s.accC[h], c);
            }
            g_R[d]  = Wv[d] * Wf[d];
            g_r0[d] = bv[d] * Wf[d];
        }
        __syncthreads();
        if (t < NH) {
            g_sA[t] = sm.s.accA[t] * 0.125f;   // 1/sqrt(64)
            g_sC[t] = sm.s.accC[t] * 0.125f;
        }
        __threadfence();
        __syncthreads();
        if (t == 0) atomicAdd(&g_cs, 1);
        return;
    }

    // ============ P producer blocks =========================================
    if (bid < BID_Q0) {
        int pb = bid - BID_P0;                   // 0..15
        int row0 = pb * 32;
        if (t < 32) {
            sm.p.sWv[t] = Wv[row0 + t];
            sm.p.sbv[t] = bv[row0 + t];
        }
        __syncthreads();
        const float* wsp = Ws + (size_t)row0 * NM + t;
        float accP = 0.f, acc0 = 0.f;
#pragma unroll
        for (int r0 = 0; r0 < 32; r0 += 16) {
            float wv[16];
#pragma unroll
            for (int u = 0; u < 16; u++)
                wv[u] = wsp[(size_t)(r0 + u) * NM];
#pragma unroll
            for (int u = 0; u < 16; u++) {
                accP = fmaf(sm.p.sWv[r0 + u], wv[u], accP);
                acc0 = fmaf(sm.p.sbv[r0 + u], wv[u], acc0);
            }
        }
        g_Pp[pb * NM + t]  = accP;
        g_p0q[pb * NM + t] = acc0;
        __threadfence();
        __syncthreads();
        if (t == 0) atomicAdd(&g_cp, 1);
        return;
    }

    // ============ Q blocks ==================================================
    if (bid < BID_MAIN0) {
        if (t == 0) spin_until(&g_cp, N_PBLK);
        __syncthreads();
        __threadfence();

        int qb = bid - BID_Q0;          // 0..7
        int d0 = qb * 64;
        int dl = t & 63;
        int mq = t >> 6;                // 0..3

        for (int idx = t; idx < 9 * NM; idx += 256) {
            int row = idx >> 8;
            int m   = idx & 255;
            if (row < NH) {
                sm.q.sc[row][m] = g_Pp[(2 * row) * NM + m] + g_Pp[(2 * row + 1) * NM + m];
            } else {
                float s = bs[m];
#pragma unroll
                for (int k = 0; k < 16; k++) s += g_p0q[k * NM + m];
                sm.q.sc[8][m] = s;
            }
        }
        __syncthreads();

        int d = d0 + dl;
        float acc[9];
#pragma unroll
        for (int i = 0; i < 9; i++) acc[i] = 0.f;

        const float* wp = We + d;
        int mbase = mq * 64;
#pragma unroll
        for (int m0 = 0; m0 < 64; m0 += 8) {
            float wv[8];
#pragma unroll
            for (int u = 0; u < 8; u++)
                wv[u] = wp[(size_t)(mbase + m0 + u) * ND];
#pragma unroll
            for (int u = 0; u < 8; u++) {
#pragma unroll
                for (int i = 0; i < 9; i++)
                    acc[i] = fmaf(sm.q.sc[i][mbase + m0 + u], wv[u], acc[i]);
            }
        }

        if (mq > 0) {
#pragma unroll
            for (int i = 0; i < 9; i++) sm.q.red[mq - 1][i][dl] = acc[i];
        }
        __syncthreads();
        if (mq == 0) {
#pragma unroll
            for (int i = 0; i < 9; i++)
                acc[i] = ((acc[i] + sm.q.red[0][i][dl]) + sm.q.red[1][i][dl]) + sm.q.red[2][i][dl];
#pragma unroll
            for (int h = 0; h < NH; h++) g_Q[h * ND + d] = acc[h];
            g_q0[d] = acc[8] + be[d];
        }
        __threadfence();
        __syncthreads();
        if (t == 0) atomicAdd(&g_cq, 1);
        return;
    }

    // ============ main blocks ===============================================
    {
        int idx = bid - BID_MAIN0;
        int c = idx & (NC - 1);
        int b = idx >> 6;
        int lane = t & 31;
        int w = t >> 5;
        const float* xp = x + (size_t)(b * NS) * NC + c;

        // load xs (independent of producers)
        if (t < NS) sm.m.xs[t] = xp[t * NC];

        // wait ONLY for the scalar block (cheap, ready almost immediately)
        if (t == 0) spin_until(&g_cs, 1);
        __syncthreads();
        __threadfence();
        if (t < NH) { sm.m.sA[t] = g_sA[t]; sm.m.sC[t] = g_sC[t]; }
        __syncthreads();

        // min/max -> expansion center
        if (t < 32) {
            float mx = -1e30f, mn = 1e30f;
#pragma unroll
            for (int k = t; k < NS; k += 32) {
                float v = sm.m.xs[k];
                mx = fmaxf(mx, v);
                mn = fminf(mn, v);
            }
#pragma unroll
            for (int o = 16; o; o >>= 1) {
                mx = fmaxf(mx, __shfl_xor_sync(0xffffffffu, mx, o));
                mn = fminf(mn, __shfl_xor_sync(0xffffffffu, mn, o));
            }
            if (t == 0) { sm.m.smax = mx; sm.m.smin = mn; }
        }
        __syncthreads();

        float xmid = 0.5f * (sm.m.smax + sm.m.smin);

        // Stage A: per-head weighted moments
        {
            float bc = fmaf(sm.m.sA[w], xmid, sm.m.sC[w]);
            float m[11];
#pragma unroll
            for (int n = 0; n < 11; n++) m[n] = 0.f;
#pragma unroll
            for (int j = 0; j < 4; j++) {
                float xk = sm.m.xs[lane + 32 * j];
                float p = __expf(bc * xk);
#pragma unroll
                for (int n = 0; n < 11; n++) { m[n] += p; p *= xk; }
            }
#pragma unroll
            for (int n = 0; n < 11; n++) m[n] = warp_sum(m[n]);
            if (lane == 0) {
                const float invf[10] = {1.f, 1.f, 0.5f, 1.f/6.f, 1.f/24.f, 1.f/120.f,
                                        1.f/720.f, 1.f/5040.f, 1.f/40320.f, 1.f/362880.f};
#pragma unroll
                for (int n = 0; n < 10; n++) {
                    sm.m.cD[w][n] = m[n]     * invf[n];
                    sm.m.cN[w][n] = m[n + 1] * invf[n];
                }
            }
        }
        __syncthreads();

        // Stage B: rational evaluation per (h,q)
#pragma unroll
        for (int p = t; p < NH * NS; p += 256) {
            int h = p >> 7;
            int q = p & (NS - 1);
            float dl = sm.m.sA[h] * (sm.m.xs[q] - xmid);
            float num = sm.m.cN[h][9];
            float den = sm.m.cD[h][9];
#pragma unroll
            for (int n = 8; n >= 0; n--) {
                num = fmaf(num, dl, sm.m.cN[h][n]);
                den = fmaf(den, dl, sm.m.cD[h][n]);
            }
            sm.m.xv[h][q] = __fdividef(num, den);
        }
        __syncthreads();

        // squeeze
        {
            float s = sm.m.xv[w][lane] + sm.m.xv[w][lane + 32]
                    + sm.m.xv[w][lane + 64] + sm.m.xv[w][lane + 96];
            s = warp_sum(s);
            if (lane == 0) sm.m.sqv[w] = s * (1.0f / NS);
        }

        // NOW wait for the Q chain (should already be complete — hidden
        // behind the moment/Horner work above)
        if (t == 0) spin_until(&g_cq, N_QBLK);
        __syncthreads();
        __threadfence();

        // excitation
        for (int d = t; d < ND; d += 256) {
            float u = g_q0[d];
#pragma unroll
            for (int h = 0; h < NH; h++)
                u = fmaf(sm.m.sqv[h], g_Q[h * ND + d], u);
            sm.m.exc[d] = __fdividef(1.0f, 1.0f + __expf(-u));
        }
        __syncthreads();

        // output projection folds
        {
            int d0 = w * NHD + lane;
            float s = g_R[d0] * sm.m.exc[d0] + g_R[d0 + 32] * sm.m.exc[d0 + 32];
            s = warp_sum(s);
            if (lane == 0) sm.m.w1[w] = s;
        }
        {
            float pv = g_r0[t] * sm.m.exc[t] + g_r0[t + 256] * sm.m.exc[t + 256];
            pv = warp_sum(pv);
            if (lane == 0) sm.m.red[w] = pv;
        }
        __syncthreads();
        if (t == 0) {
            float s = 0.f;
#pragma unroll
            for (int i = 0; i < 8; i++) s += sm.m.red[i];
            sm.m.w0t = s + bf[0];
        }
        __syncthreads();

        if (t < NS) {
            float o = sm.m.w0t;
#pragma unroll
            for (int h = 0; h < NH; h++)
                o = fmaf(sm.m.xv[h][t], sm.m.w1[h], o);
            out[(size_t)(b * NS + t) * NC + c] = o;
        }

        // completion + counter reset by the last main block (for next launch)
        __syncthreads();
        if (t == 0) {
            int v = atomicAdd(&g_done, 1);
            if (v == N_MAIN - 1) {
                g_cs = 0;
                g_cp = 0;
                g_cq = 0;
                g_done = 0;
            }
        }
    }
}

// ---------------- launch ----------------------------------------------------
extern "C" void kernel_launch(void* const* d_in, const int* in_sizes, int n_in,
                              void* d_out, int out_size)
{
    const float* x  = (const float*)d_in[0];
    const float* Wq = (const float*)d_in[1];
    const float* bq = (const float*)d_in[2];
    const float* Wk = (const float*)d_in[3];
    // d_in[4] = bk: cancels under softmax, unused
    const float* Wv = (const float*)d_in[5];
    const float* bv = (const float*)d_in[6];
    const float* Ws = (const float*)d_in[7];
    const float* bs = (const float*)d_in[8];
    const float* We = (const float*)d_in[9];
    const float* be = (const float*)d_in[10];
    const float* Wf = (const float*)d_in[11];
    const float* bf = (const float*)d_in[12];
    float* out = (float*)d_out;

    k_fused<<<GRID_TOT, 256>>>(x, Wq, bq, Wk, Wv, bv, Ws, bs, We, be, Wf, bf, out);
}

// round 8
// speedup vs baseline: 1.2741x; 1.0611x over previous
#include <cuda_runtime.h>

// Problem constants
#define NB 16
#define NS 128
#define NC 64
#define NH 8
#define NHD 64
#define ND 512
#define NM 256   // D/2

// Role layout in the single grid
#define BID_SCAL 0
#define BID_P0 1
#define N_PBLK 16
#define BID_Q0 17
#define N_QBLK 8
#define BID_MAIN0 25
#define N_MAINBLK 512                      // each handles 2 (b,c) units
#define GRID_TOT (BID_MAIN0 + N_MAINBLK)   // 537

// ---------------- scratch (device globals; zero-initialized) ----------------
__device__ float g_sA[NH];
__device__ float g_sC[NH];
__device__ float g_Pp[16 * NM];
__device__ float g_p0q[16 * NM];
__device__ float g_Q[NH * ND];
__device__ float g_q0[ND];
__device__ float g_R[ND];
__device__ float g_r0[ND];
__device__ int   g_cs, g_cp, g_cq, g_done;

__device__ __forceinline__ float warp_sum(float v) {
#pragma unroll
    for (int o = 16; o; o >>= 1) v += __shfl_xor_sync(0xffffffffu, v, o);
    return v;
}

__device__ __forceinline__ void spin_until(volatile int* ctr, int target) {
    while (*ctr < target) __nanosleep(64);
}

struct SmP { float sWv[32], sbv[32]; };
struct SmS { float accA[NH], accC[NH]; };
struct SmQ { float sc[9][NM]; float red[3][9][64]; };
struct SmM {
    float xs[NS]; float xv[NH][NS]; float exc[ND];
    float sqv[NH], w1[NH], red[8];
};

__global__ void __launch_bounds__(256) k_fused(
    const float* __restrict__ x,
    const float* __restrict__ Wq, const float* __restrict__ bq,
    const float* __restrict__ Wk,
    const float* __restrict__ Wv, const float* __restrict__ bv,
    const float* __restrict__ Ws, const float* __restrict__ bs,
    const float* __restrict__ We, const float* __restrict__ be,
    const float* __restrict__ Wf, const float* __restrict__ bf,
    float* __restrict__ out)
{
    __shared__ union { SmP p; SmS s; SmQ q; SmM m; } sm;
    int t = threadIdx.x;
    int bid = blockIdx.x;

    // ============ scalar block ==============================================
    if (bid == BID_SCAL) {
        if (t < NH) { sm.s.accA[t] = 0.f; sm.s.accC[t] = 0.f; }
        __syncthreads();
        int lane = t & 31;
#pragma unroll
        for (int seg = 0; seg < 2; seg++) {
            int d = t + seg * 256;
            float a = Wq[d] * Wk[d];
            float c = bq[d] * Wk[d];
            a = warp_sum(a);
            c = warp_sum(c);
            if (lane == 0) {
                int h = d >> 6;
                atomicAdd(&sm.s.accA[h], a);
                atomicAdd(&sm.s.accC[h], c);
            }
            g_R[d]  = Wv[d] * Wf[d];
            g_r0[d] = bv[d] * Wf[d];
        }
        __syncthreads();
        if (t < NH) {
            g_sA[t] = sm.s.accA[t] * 0.125f;
            g_sC[t] = sm.s.accC[t] * 0.125f;
        }
        __threadfence();
        __syncthreads();
        if (t == 0) atomicAdd(&g_cs, 1);
        return;
    }

    // ============ P producer blocks =========================================
    if (bid < BID_Q0) {
        int pb = bid - BID_P0;
        int row0 = pb * 32;
        if (t < 32) {
            sm.p.sWv[t] = Wv[row0 + t];
            sm.p.sbv[t] = bv[row0 + t];
        }
        __syncthreads();
        const float* wsp = Ws + (size_t)row0 * NM + t;
        float accP = 0.f, acc0 = 0.f;
#pragma unroll
        for (int r0 = 0; r0 < 32; r0 += 16) {
            float wv[16];
#pragma unroll
            for (int u = 0; u < 16; u++)
                wv[u] = wsp[(size_t)(r0 + u) * NM];
#pragma unroll
            for (int u = 0; u < 16; u++) {
                accP = fmaf(sm.p.sWv[r0 + u], wv[u], accP);
                acc0 = fmaf(sm.p.sbv[r0 + u], wv[u], acc0);
            }
        }
        g_Pp[pb * NM + t]  = accP;
        g_p0q[pb * NM + t] = acc0;
        __threadfence();
        __syncthreads();
        if (t == 0) atomicAdd(&g_cp, 1);
        return;
    }

    // ============ Q blocks ==================================================
    if (bid < BID_MAIN0) {
        if (t == 0) spin_until(&g_cp, N_PBLK);
        __syncthreads();
        __threadfence();

        int qb = bid - BID_Q0;
        int d0 = qb * 64;
        int dl = t & 63;
        int mq = t >> 6;

        for (int idx = t; idx < 9 * NM; idx += 256) {
            int row = idx >> 8;
            int m   = idx & 255;
            if (row < NH) {
                sm.q.sc[row][m] = g_Pp[(2 * row) * NM + m] + g_Pp[(2 * row + 1) * NM + m];
            } else {
                float s = bs[m];
#pragma unroll
                for (int k = 0; k < 16; k++) s += g_p0q[k * NM + m];
                sm.q.sc[8][m] = s;
            }
        }
        __syncthreads();

        int d = d0 + dl;
        float acc[9];
#pragma unroll
        for (int i = 0; i < 9; i++) acc[i] = 0.f;

        const float* wp = We + d;
        int mbase = mq * 64;
#pragma unroll
        for (int m0 = 0; m0 < 64; m0 += 8) {
            float wv[8];
#pragma unroll
            for (int u = 0; u < 8; u++)
                wv[u] = wp[(size_t)(mbase + m0 + u) * ND];
#pragma unroll
            for (int u = 0; u < 8; u++) {
#pragma unroll
                for (int i = 0; i < 9; i++)
                    acc[i] = fmaf(sm.q.sc[i][mbase + m0 + u], wv[u], acc[i]);
            }
        }

        if (mq > 0) {
#pragma unroll
            for (int i = 0; i < 9; i++) sm.q.red[mq - 1][i][dl] = acc[i];
        }
        __syncthreads();
        if (mq == 0) {
#pragma unroll
            for (int i = 0; i < 9; i++)
                acc[i] = ((acc[i] + sm.q.red[0][i][dl]) + sm.q.red[1][i][dl]) + sm.q.red[2][i][dl];
#pragma unroll
            for (int h = 0; h < NH; h++) g_Q[h * ND + d] = acc[h];
            g_q0[d] = acc[8] + be[d];
        }
        __threadfence();
        __syncthreads();
        if (t == 0) atomicAdd(&g_cq, 1);
        return;
    }

    // ============ main blocks: 2 (b,c) units each ===========================
    {
        int idx = bid - BID_MAIN0;        // 0..511
        int b = idx >> 5;                 // 16 b
        int cpair = idx & 31;             // 32 c-pairs
        int lane = t & 31;
        int w = t >> 5;                   // warp == head

        if (t == 0) spin_until(&g_cs, 1);
        // (sync below covers the spin for all threads)

        float sa = 0.f, sc_ = 0.f;        // loaded after first sync
        bool got_q = false;

#pragma unroll
        for (int u = 0; u < 2; u++) {
            int c = cpair * 2 + u;
            const float* xp = x + (size_t)(b * NS) * NC + c;
            if (t < NS) sm.m.xs[t] = xp[t * NC];
            __syncthreads();                               // (1) xs + scalars ready
            if (u == 0) {
                __threadfence();
                sa  = g_sA[w];
                sc_ = g_sC[w];
            }

            // per-warp: fetch this warp's 4 x values
            float x0 = sm.m.xs[lane];
            float x1 = sm.m.xs[lane + 32];
            float x2 = sm.m.xs[lane + 64];
            float x3 = sm.m.xs[lane + 96];

            // redundant per-warp min/max (same op order as before -> same value)
            float mx = fmaxf(fmaxf(x0, x1), fmaxf(x2, x3));
            float mn = fminf(fminf(x0, x1), fminf(x2, x3));
#pragma unroll
            for (int o = 16; o; o >>= 1) {
                mx = fmaxf(mx, __shfl_xor_sync(0xffffffffu, mx, o));
                mn = fminf(mn, __shfl_xor_sync(0xffffffffu, mn, o));
            }
            float xmid = 0.5f * (mx + mn);
            float bc = fmaf(sa, xmid, sc_);

            // moments M0..M8 of weights exp(bc*xk)
            float m0 = 0.f, m1 = 0.f, m2 = 0.f, m3 = 0.f, m4 = 0.f,
                  m5 = 0.f, m6 = 0.f, m7 = 0.f, m8 = 0.f;
#define MOMSTEP(xk) do { float p = __expf(bc * (xk)); \
            m0 += p; p *= (xk); m1 += p; p *= (xk); m2 += p; p *= (xk); \
            m3 += p; p *= (xk); m4 += p; p *= (xk); m5 += p; p *= (xk); \
            m6 += p; p *= (xk); m7 += p; p *= (xk); m8 += p; } while (0)
            MOMSTEP(x0); MOMSTEP(x1); MOMSTEP(x2); MOMSTEP(x3);
#undef MOMSTEP
            m0 = warp_sum(m0); m1 = warp_sum(m1); m2 = warp_sum(m2);
            m3 = warp_sum(m3); m4 = warp_sum(m4); m5 = warp_sum(m5);
            m6 = warp_sum(m6); m7 = warp_sum(m7); m8 = warp_sum(m8);

            const float i2 = 0.5f, i3 = 1.f/6.f, i4 = 1.f/24.f, i5 = 1.f/120.f,
                        i6 = 1.f/720.f, i7 = 1.f/5040.f;
            float cd0 = m0,      cd1 = m1,      cd2 = m2 * i2, cd3 = m3 * i3,
                  cd4 = m4 * i4, cd5 = m5 * i5, cd6 = m6 * i6, cd7 = m7 * i7;
            float cn0 = m1,      cn1 = m2,      cn2 = m3 * i2, cn3 = m4 * i3,
                  cn4 = m5 * i4, cn5 = m6 * i5, cn6 = m7 * i6, cn7 = m8 * i7;

            // stage B: 4 tasks for this head (q = lane + 32j), coeffs in regs
            float f0, f1, f2, f3;
#define HORNER(xq, fout) do { \
            float dl = sa * ((xq) - xmid); \
            float num = fmaf(cn7, dl, cn6); num = fmaf(num, dl, cn5); \
            num = fmaf(num, dl, cn4); num = fmaf(num, dl, cn3); \
            num = fmaf(num, dl, cn2); num = fmaf(num, dl, cn1); \
            num = fmaf(num, dl, cn0); \
            float den = fmaf(cd7, dl, cd6); den = fmaf(den, dl, cd5); \
            den = fmaf(den, dl, cd4); den = fmaf(den, dl, cd3); \
            den = fmaf(den, dl, cd2); den = fmaf(den, dl, cd1); \
            den = fmaf(den, dl, cd0); \
            fout = __fdividef(num, den); } while (0)
            HORNER(x0, f0); HORNER(x1, f1); HORNER(x2, f2); HORNER(x3, f3);
#undef HORNER
            sm.m.xv[w][lane]      = f0;
            sm.m.xv[w][lane + 32] = f1;
            sm.m.xv[w][lane + 64] = f2;
            sm.m.xv[w][lane + 96] = f3;

            // squeeze directly from registers (same order as smem version)
            {
                float s = ((f0 + f1) + f2) + f3;
                s = warp_sum(s);
                if (lane == 0) sm.m.sqv[w] = s * (1.0f / NS);
            }

            // first unit: make sure the Q chain has landed (hidden by above)
            if (u == 0 && !got_q) {
                if (t == 0) spin_until(&g_cq, N_QBLK);
                got_q = true;
            }
            __syncthreads();                               // (2) xv, sqv, Q ready
            if (u == 0) __threadfence();

            // excitation
            for (int d = t; d < ND; d += 256) {
                float uu = g_q0[d];
#pragma unroll
                for (int h = 0; h < NH; h++)
                    uu = fmaf(sm.m.sqv[h], g_Q[h * ND + d], uu);
                sm.m.exc[d] = __fdividef(1.0f, 1.0f + __expf(-uu));
            }
            __syncthreads();                               // (3) exc ready

            // folds
            {
                int d0 = w * NHD + lane;
                float s = g_R[d0] * sm.m.exc[d0] + g_R[d0 + 32] * sm.m.exc[d0 + 32];
                s = warp_sum(s);
                if (lane == 0) sm.m.w1[w] = s;
            }
            {
                float pv = g_r0[t] * sm.m.exc[t] + g_r0[t + 256] * sm.m.exc[t + 256];
                pv = warp_sum(pv);
                if (lane == 0) sm.m.red[w] = pv;
            }
            __syncthreads();                               // (4) w1, red ready

            if (t < NS) {
                float w0t = ((((((((sm.m.red[0] + sm.m.red[1]) + sm.m.red[2])
                              + sm.m.red[3]) + sm.m.red[4]) + sm.m.red[5])
                              + sm.m.red[6]) + sm.m.red[7])) + bf[0];
                float o = w0t;
#pragma unroll
                for (int h = 0; h < NH; h++)
                    o = fmaf(sm.m.xv[h][t], sm.m.w1[h], o);
                out[(size_t)(b * NS + t) * NC + c] = o;
            }
            // next unit's sync(1) orders the xs overwrite; xv/w1/red clobbers
            // happen only after that barrier.
        }

        // completion + counter reset
        __syncthreads();
        if (t == 0) {
            int v = atomicAdd(&g_done, 1);
            if (v == N_MAINBLK - 1) {
                g_cs = 0;
                g_cp = 0;
                g_cq = 0;
                g_done = 0;
            }
        }
    }
}

// ---------------- launch ----------------------------------------------------
extern "C" void kernel_launch(void* const* d_in, const int* in_sizes, int n_in,
                              void* d_out, int out_size)
{
    const float* x  = (const float*)d_in[0];
    const float* Wq = (const float*)d_in[1];
    const float* bq = (const float*)d_in[2];
    const float* Wk = (const float*)d_in[3];
    // d_in[4] = bk: cancels under softmax, unused
    const float* Wv = (const float*)d_in[5];
    const float* bv = (const float*)d_in[6];
    const float* Ws = (const float*)d_in[7];
    const float* bs = (const float*)d_in[8];
    const float* We = (const float*)d_in[9];
    const float* be = (const float*)d_in[10];
    const float* Wf = (const float*)d_in[11];
    const float* bf = (const float*)d_in[12];
    float* out = (float*)d_out;

    k_fused<<<GRID_TOT, 256>>>(x, Wq, bq, Wk, Wv, bv, Ws, bs, We, be, Wf, bf, out);
}

// round 10
// speedup vs baseline: 1.3632x; 1.0699x over previous
#include <cuda_runtime.h>

// Problem constants
#define NB 16
#define NS 128
#define NC 64
#define NH 8
#define NHD 64
#define ND 512
#define NM 256   // D/2

// Role layout in the single grid
#define BID_SCAL 0
#define BID_P0 1
#define N_PBLK 32                          // 16 rows of Ws each
#define BID_Q0 33
#define N_QBLK 16                          // 32 d-columns each
#define BID_MAIN0 49
#define N_MAIN (NB * NC)                   // 1024
#define GRID_TOT (BID_MAIN0 + N_MAIN)      // 1073

// ---------------- scratch (device globals; zero-initialized) ----------------
__device__ float g_sA[NH];
__device__ float g_sC[NH];
__device__ float g_Pp[N_PBLK * NM];   // P partials per 16-row chunk
__device__ float g_p0q[N_PBLK * NM];  // p0 partials (bv @ Ws)
__device__ float g_Q[NH * ND];
__device__ float g_q0[ND];
__device__ float g_R[ND];
__device__ float g_r0[ND];
__device__ int   g_cs, g_cp, g_cq, g_done;

__device__ __forceinline__ float warp_sum(float v) {
#pragma unroll
    for (int o = 16; o; o >>= 1) v += __shfl_xor_sync(0xffffffffu, v, o);
    return v;
}

__device__ __forceinline__ void spin_until(volatile int* ctr, int target) {
    while (*ctr < target) __nanosleep(64);
}

struct SmP { float sWv[16], sbv[16]; };
struct SmS { float accA[NH], accC[NH]; };
struct SmQ { float sc[9][NM]; float red[7][9][32]; };
struct SmM { float xs[NS]; float xv[NH][NS]; float sqv[NH], w1[NH], red[8]; };

__global__ void __launch_bounds__(256) k_fused(
    const float* __restrict__ x,
    const float* __restrict__ Wq, const float* __restrict__ bq,
    const float* __restrict__ Wk,
    const float* __restrict__ Wv, const float* __restrict__ bv,
    const float* __restrict__ Ws, const float* __restrict__ bs,
    const float* __restrict__ We, const float* __restrict__ be,
    const float* __restrict__ Wf, const float* __restrict__ bf,
    float* __restrict__ out)
{
    __shared__ union { SmP p; SmS s; SmQ q; SmM m; } sm;
    int t = threadIdx.x;
    int bid = blockIdx.x;
    int lane = t & 31;
    int w = t >> 5;

    // ============ scalar block ==============================================
    if (bid == BID_SCAL) {
        if (t < NH) { sm.s.accA[t] = 0.f; sm.s.accC[t] = 0.f; }
        __syncthreads();
#pragma unroll
        for (int seg = 0; seg < 2; seg++) {
            int d = t + seg * 256;
            float a = Wq[d] * Wk[d];
            float c = bq[d] * Wk[d];
            a = warp_sum(a);
            c = warp_sum(c);
            if (lane == 0) {
                int h = d >> 6;
                atomicAdd(&sm.s.accA[h], a);
                atomicAdd(&sm.s.accC[h], c);
            }
            g_R[d]  = Wv[d] * Wf[d];
            g_r0[d] = bv[d] * Wf[d];
        }
        __syncthreads();
        if (t < NH) {
            g_sA[t] = sm.s.accA[t] * 0.125f;
            g_sC[t] = sm.s.accC[t] * 0.125f;
        }
        __threadfence();
        __syncthreads();
        if (t == 0) atomicAdd(&g_cs, 1);
        return;
    }

    // ============ P producer blocks (32 blocks x 16 rows) ===================
    if (bid < BID_Q0) {
        int pb = bid - BID_P0;
        int row0 = pb * 16;
        if (t < 16) {
            sm.p.sWv[t] = Wv[row0 + t];
            sm.p.sbv[t] = bv[row0 + t];
        }
        __syncthreads();
        const float* wsp = Ws + (size_t)row0 * NM + t;
        float wv[16];
#pragma unroll
        for (int u = 0; u < 16; u++)
            wv[u] = wsp[(size_t)u * NM];          // 16 loads in flight
        float accP = 0.f, acc0 = 0.f;
#pragma unroll
        for (int u = 0; u < 16; u++) {
            accP = fmaf(sm.p.sWv[u], wv[u], accP);
            acc0 = fmaf(sm.p.sbv[u], wv[u], acc0);
        }
        g_Pp[pb * NM + t]  = accP;
        g_p0q[pb * NM + t] = acc0;
        __threadfence();
        __syncthreads();
        if (t == 0) atomicAdd(&g_cp, 1);
        return;
    }

    // ============ Q blocks (16 blocks x 32 d-columns) =======================
    if (bid < BID_MAIN0) {
        if (t == 0) spin_until(&g_cp, N_PBLK);
        __syncthreads();
        __threadfence();

        int qb = bid - BID_Q0;            // 0..15
        int d0 = qb * 32;
        int dl = t & 31;                  // d within chunk
        int mq = t >> 5;                  // 0..7 m-eighth

        // stage P (4-way per head, fixed order) and p0 (32 partials)
        for (int idx = t; idx < 9 * NM; idx += 256) {
            int row = idx >> 8;
            int m   = idx & 255;
            if (row < NH) {
                int p4 = row * 4;
                sm.q.sc[row][m] = (g_Pp[p4 * NM + m] + g_Pp[(p4 + 1) * NM + m])
                                + (g_Pp[(p4 + 2) * NM + m] + g_Pp[(p4 + 3) * NM + m]);
            } else {
                float s = bs[m];
#pragma unroll
                for (int k = 0; k < N_PBLK; k++) s += g_p0q[k * NM + m];
                sm.q.sc[8][m] = s;
            }
        }
        __syncthreads();

        int d = d0 + dl;
        float acc[9];
#pragma unroll
        for (int i = 0; i < 9; i++) acc[i] = 0.f;

        const float* wp = We + d;
        int mbase = mq * 32;
#pragma unroll
        for (int m0 = 0; m0 < 32; m0 += 16) {
            float wv[16];
#pragma unroll
            for (int u = 0; u < 16; u++)
                wv[u] = wp[(size_t)(mbase + m0 + u) * ND];   // 16 in flight
#pragma unroll
            for (int u = 0; u < 16; u++) {
#pragma unroll
                for (int i = 0; i < 9; i++)
                    acc[i] = fmaf(sm.q.sc[i][mbase + m0 + u], wv[u], acc[i]);
            }
        }

        if (mq > 0) {
#pragma unroll
            for (int i = 0; i < 9; i++) sm.q.red[mq - 1][i][dl] = acc[i];
        }
        __syncthreads();
        if (mq == 0) {
#pragma unroll
            for (int k = 0; k < 7; k++)
#pragma unroll
                for (int i = 0; i < 9; i++)
                    acc[i] += sm.q.red[k][i][dl];
#pragma unroll
            for (int h = 0; h < NH; h++) g_Q[h * ND + d] = acc[h];
            g_q0[d] = acc[8] + be[d];
        }
        __threadfence();
        __syncthreads();
        if (t == 0) atomicAdd(&g_cq, 1);
        return;
    }

    // ============ main blocks: 1 (b,c) unit each ============================
    {
        int idx = bid - BID_MAIN0;        // 0..1023
        int c = idx & (NC - 1);
        int b = idx >> 6;
        const float* xp = x + (size_t)(b * NS) * NC + c;

        if (t < NS) sm.m.xs[t] = xp[t * NC];
        if (t == 0) spin_until(&g_cs, 1);
        __syncthreads();                                   // (1) xs + scalars
        __threadfence();

        float sa = g_sA[w], sc_ = g_sC[w];

        // this warp's 4 x values (warp == head)
        float x0 = sm.m.xs[lane];
        float x1 = sm.m.xs[lane + 32];
        float x2 = sm.m.xs[lane + 64];
        float x3 = sm.m.xs[lane + 96];

        // per-warp min/max (redundant across warps, identical values)
        float mx = fmaxf(fmaxf(x0, x1), fmaxf(x2, x3));
        float mn = fminf(fminf(x0, x1), fminf(x2, x3));
#pragma unroll
        for (int o = 16; o; o >>= 1) {
            mx = fmaxf(mx, __shfl_xor_sync(0xffffffffu, mx, o));
            mn = fminf(mn, __shfl_xor_sync(0xffffffffu, mn, o));
        }
        float xmid = 0.5f * (mx + mn);
        float bc = fmaf(sa, xmid, sc_);

        // moments M0..M6 of weights exp(bc*xk)
        float m0 = 0.f, m1 = 0.f, m2 = 0.f, m3 = 0.f, m4 = 0.f, m5 = 0.f, m6 = 0.f;
#define MOMSTEP(xk) do { float p = __expf(bc * (xk)); \
        m0 += p; p *= (xk); m1 += p; p *= (xk); m2 += p; p *= (xk); \
        m3 += p; p *= (xk); m4 += p; p *= (xk); m5 += p; p *= (xk); m6 += p; } while (0)
        MOMSTEP(x0); MOMSTEP(x1); MOMSTEP(x2); MOMSTEP(x3);
#undef MOMSTEP
        m0 = warp_sum(m0); m1 = warp_sum(m1); m2 = warp_sum(m2);
        m3 = warp_sum(m3); m4 = warp_sum(m4); m5 = warp_sum(m5);
        m6 = warp_sum(m6);

        const float i2 = 0.5f, i3 = 1.f/6.f, i4 = 1.f/24.f, i5 = 1.f/120.f;
        float cd0 = m0,      cd1 = m1,      cd2 = m2 * i2,
              cd3 = m3 * i3, cd4 = m4 * i4, cd5 = m5 * i5;
        float cn0 = m1,      cn1 = m2,      cn2 = m3 * i2,
              cn3 = m4 * i3, cn4 = m5 * i4, cn5 = m6 * i5;

        // stage B: degree-5 rational, coeffs in registers
        float f0, f1, f2, f3;
#define HORNER(xq, fout) do { \
        float dl = sa * ((xq) - xmid); \
        float num = fmaf(cn5, dl, cn4); num = fmaf(num, dl, cn3); \
        num = fmaf(num, dl, cn2); num = fmaf(num, dl, cn1); \
        num = fmaf(num, dl, cn0); \
        float den = fmaf(cd5, dl, cd4); den = fmaf(den, dl, cd3); \
        den = fmaf(den, dl, cd2); den = fmaf(den, dl, cd1); \
        den = fmaf(den, dl, cd0); \
        fout = __fdividef(num, den); } while (0)
        HORNER(x0, f0); HORNER(x1, f1); HORNER(x2, f2); HORNER(x3, f3);
#undef HORNER
        sm.m.xv[w][lane]      = f0;
        sm.m.xv[w][lane + 32] = f1;
        sm.m.xv[w][lane + 64] = f2;
        sm.m.xv[w][lane + 96] = f3;

        // squeeze from registers
        {
            float s = ((f0 + f1) + f2) + f3;
            s = warp_sum(s);
            if (lane == 0) sm.m.sqv[w] = s * (1.0f / NS);
        }

        if (t == 0) spin_until(&g_cq, N_QBLK);            // usually already done
        __syncthreads();                                   // (2) sqv, xv, Q
        __threadfence();

        // excitation: warp-local d range [64w, 64w+64), e0/e1 stay in regs
        {
            int d0 = w * NHD + lane;
            float u0 = g_q0[d0];
            float u1 = g_q0[d0 + 32];
#pragma unroll
            for (int h = 0; h < NH; h++) {
                float sv = sm.m.sqv[h];
                u0 = fmaf(sv, g_Q[h * ND + d0], u0);
                u1 = fmaf(sv, g_Q[h * ND + d0 + 32], u1);
            }
            float e0 = __fdividef(1.0f, 1.0f + __expf(-u0));
            float e1 = __fdividef(1.0f, 1.0f + __expf(-u1));

            float ws_ = g_R[d0] * e0 + g_R[d0 + 32] * e1;
            ws_ = warp_sum(ws_);
            if (lane == 0) sm.m.w1[w] = ws_;

            float rs = g_r0[d0] * e0 + g_r0[d0 + 32] * e1;
            rs = warp_sum(rs);
            if (lane == 0) sm.m.red[w] = rs;
        }
        __syncthreads();                                   // (3) w1, red

        if (t < NS) {
            float w0t = ((((((((sm.m.red[0] + sm.m.red[1]) + sm.m.red[2])
                          + sm.m.red[3]) + sm.m.red[4]) + sm.m.red[5])
                          + sm.m.red[6]) + sm.m.red[7])) + bf[0];
            float o = w0t;
#pragma unroll
            for (int h = 0; h < NH; h++)
                o = fmaf(sm.m.xv[h][t], sm.m.w1[h], o);
            out[(size_t)(b * NS + t) * NC + c] = o;
        }

        // completion + counter reset by last main block
        __syncthreads();
        if (t == 0) {
            int v = atomicAdd(&g_done, 1);
            if (v == N_MAIN - 1) {
                g_cs = 0;
                g_cp = 0;
                g_cq = 0;
                g_done = 0;
            }
        }
    }
}

// ---------------- launch ----------------------------------------------------
extern "C" void kernel_launch(void* const* d_in, const int* in_sizes, int n_in,
                              void* d_out, int out_size)
{
    const float* x  = (const float*)d_in[0];
    const float* Wq = (const float*)d_in[1];
    const float* bq = (const float*)d_in[2];
    const float* Wk = (const float*)d_in[3];
    // d_in[4] = bk: cancels under softmax, unused
    const float* Wv = (const float*)d_in[5];
    const float* bv = (const float*)d_in[6];
    const float* Ws = (const float*)d_in[7];
    const float* bs = (const float*)d_in[8];
    const float* We = (const float*)d_in[9];
    const float* be = (const float*)d_in[10];
    const float* Wf = (const float*)d_in[11];
    const float* bf = (const float*)d_in[12];
    float* out = (float*)d_out;

    k_fused<<<GRID_TOT, 256>>>(x, Wq, bq, Wk, Wv, bv, Ws, bs, We, be, Wf, bf, out);
}